// round 5
// baseline (speedup 1.0000x reference)
#include <cuda_runtime.h>
#include <math.h>

#define BATCH 32
#define WG 640
#define HG 480
#define WH (WG*HG)          /* 307200 */
#define IMG_H 480
#define IMG_W 640

__device__ float g_Ki[9];
__device__ float g_max;

// One-thread setup: 3x3 inverse of K (adjugate / det) + reset the global max.
__global__ void k_init(const float* __restrict__ K) {
    float a=K[0],b=K[1],c=K[2],d=K[3],e=K[4],f=K[5],g=K[6],h=K[7],i=K[8];
    float det = a*(e*i - f*h) - b*(d*i - f*g) + c*(d*h - e*g);
    float id = 1.0f/det;
    g_Ki[0]=(e*i-f*h)*id; g_Ki[1]=(c*h-b*i)*id; g_Ki[2]=(b*f-c*e)*id;
    g_Ki[3]=(f*g-d*i)*id; g_Ki[4]=(a*i-c*g)*id; g_Ki[5]=(c*d-a*f)*id;
    g_Ki[6]=(d*h-e*g)*id; g_Ki[7]=(b*g-a*h)*id; g_Ki[8]=(a*e-b*d)*id;
    g_max = -INFINITY;
}

// Faithful step-by-step uv computation (matches reference's chain of fp32 einsums):
// ray = [x,y,1] @ K^-1 ; p = d*ray ; t = [p,1] @ T (first 3 cols) ; q = t @ K ;
// uv = (q0,q1)/(q2 + 1e-4)
__device__ __forceinline__ void uv_of(float d, float x, float y,
    const float* __restrict__ Ki, const float* __restrict__ Km,
    const float* __restrict__ T, float& u, float& v)
{
    float r0 = x*Ki[0] + y*Ki[3] + Ki[6];
    float r1 = x*Ki[1] + y*Ki[4] + Ki[7];
    float r2 = x*Ki[2] + y*Ki[5] + Ki[8];
    float p0 = d*r0, p1 = d*r1, p2 = d*r2;
    float t0 = p0*T[0] + p1*T[4] + p2*T[8]  + T[12];
    float t1 = p0*T[1] + p1*T[5] + p2*T[9]  + T[13];
    float t2 = p0*T[2] + p1*T[6] + p2*T[10] + T[14];
    float q0 = t0*Km[0] + t1*Km[3] + t2*Km[6];
    float q1 = t0*Km[1] + t1*Km[4] + t2*Km[7];
    float q2 = t0*Km[2] + t1*Km[5] + t2*Km[8];
    float inv = 1.0f/(q2 + 1e-4f);
    u = q0*inv;
    v = q1*inv;
}

__global__ __launch_bounds__(256) void k_pass1(
    const float* __restrict__ depth, const float* __restrict__ trans,
    const float* __restrict__ Kp)
{
    int b = blockIdx.y;
    int t = blockIdx.x*256 + threadIdx.x;
    int pix = t*4;
    int w = pix/HG;
    int h = pix - w*HG;

    float Ki[9], Km[9], T[16];
    #pragma unroll
    for (int i=0;i<9;i++){ Ki[i]=g_Ki[i]; Km[i]=__ldg(Kp+i); }
    #pragma unroll
    for (int i=0;i<16;i++) T[i]=__ldg(trans + b*16 + i);

    float4 d4 = *reinterpret_cast<const float4*>(depth + (size_t)b*WH + pix);
    float dd[4] = {d4.x, d4.y, d4.z, d4.w};

    float m = -INFINITY;
    float y = (float)w;
    #pragma unroll
    for (int k=0;k<4;k++){
        float u,v;
        uv_of(dd[k], (float)(h+k), y, Ki, Km, T, u, v);
        m = fmaxf(m, fmaxf(u,v));
    }
    #pragma unroll
    for (int o=16;o>0;o>>=1) m = fmaxf(m, __shfl_xor_sync(0xffffffffu, m, o));

    __shared__ float sm[8];
    if ((threadIdx.x & 31)==0) sm[threadIdx.x>>5] = m;
    __syncthreads();
    if (threadIdx.x==0){
        float bm = sm[0];
        #pragma unroll
        for (int i=1;i<8;i++) bm = fmaxf(bm, sm[i]);
        // float atomic max via int/uint ordering trick (init = -inf)
        if (bm >= 0.0f) atomicMax((int*)&g_max, __float_as_int(bm));
        else            atomicMin((unsigned int*)&g_max, __float_as_uint(bm));
    }
}

__global__ __launch_bounds__(256) void k_pass2(
    const float* __restrict__ depth, const float* __restrict__ trans,
    const float* __restrict__ Kp, const float* __restrict__ img,
    float* __restrict__ out)
{
    int b = blockIdx.y;
    int t = blockIdx.x*256 + threadIdx.x;
    int pix = t*4;
    int w = pix/HG;
    int h = pix - w*HG;

    float Ki[9], Km[9], T[16];
    #pragma unroll
    for (int i=0;i<9;i++){ Ki[i]=g_Ki[i]; Km[i]=__ldg(Kp+i); }
    #pragma unroll
    for (int i=0;i<16;i++) T[i]=__ldg(trans + b*16 + i);

    float M = g_max;
    float4 d4 = *reinterpret_cast<const float4*>(depth + (size_t)b*WH + pix);
    float dd[4] = {d4.x, d4.y, d4.z, d4.w};

    const float* imgb = img + (size_t)b*3*WH;
    float res[3][4];
    float y = (float)w;

    #pragma unroll
    for (int k=0;k<4;k++){
        float u,v;
        uv_of(dd[k], (float)(h+k), y, Ki, Km, T, u, v);
        // normalization exactly as in reference: 2*(uv/max) - 1
        float un = 2.0f*(u/M) - 1.0f;
        float vn = 2.0f*(v/M) - 1.0f;
        // grid_sample, align_corners=False, padding_mode='zeros'
        float xs = (un + 1.0f)*(0.5f*IMG_W) - 0.5f;
        float ys = (vn + 1.0f)*(0.5f*IMG_H) - 0.5f;
        float x0f = floorf(xs), y0f = floorf(ys);
        float wx = xs - x0f,   wy = ys - y0f;
        float x1f = x0f + 1.0f, y1f = y0f + 1.0f;
        bool vx0 = (x0f >= 0.0f) && (x0f <= (float)(IMG_W-1));
        bool vx1 = (x1f >= 0.0f) && (x1f <= (float)(IMG_W-1));
        bool vy0 = (y0f >= 0.0f) && (y0f <= (float)(IMG_H-1));
        bool vy1 = (y1f >= 0.0f) && (y1f <= (float)(IMG_H-1));
        int x0i = (int)fminf(fmaxf(x0f,0.0f),(float)(IMG_W-1));
        int x1i = (int)fminf(fmaxf(x1f,0.0f),(float)(IMG_W-1));
        int y0i = (int)fminf(fmaxf(y0f,0.0f),(float)(IMG_H-1));
        int y1i = (int)fminf(fmaxf(y1f,0.0f),(float)(IMG_H-1));
        float w00 = (1.0f-wx)*(1.0f-wy);
        float w01 = wx*(1.0f-wy);
        float w10 = (1.0f-wx)*wy;
        float w11 = wx*wy;
        int i00 = y0i*IMG_W + x0i;
        int i01 = y0i*IMG_W + x1i;
        int i10 = y1i*IMG_W + x0i;
        int i11 = y1i*IMG_W + x1i;
        bool b00 = vx0 && vy0, b01 = vx1 && vy0, b10 = vx0 && vy1, b11 = vx1 && vy1;
        #pragma unroll
        for (int c=0;c<3;c++){
            const float* ic = imgb + (size_t)c*WH;
            float s = 0.0f;
            if (b00) s += __ldg(ic + i00) * w00;
            if (b01) s += __ldg(ic + i01) * w01;
            if (b10) s += __ldg(ic + i10) * w10;
            if (b11) s += __ldg(ic + i11) * w11;
            res[c][k] = s;
        }
    }

    size_t ob = (size_t)b*3*WH + (size_t)w*HG + (size_t)h;
    #pragma unroll
    for (int c=0;c<3;c++){
        float4 o = make_float4(res[c][0], res[c][1], res[c][2], res[c][3]);
        *reinterpret_cast<float4*>(out + ob + (size_t)c*WH) = o;
    }
}

extern "C" void kernel_launch(void* const* d_in, const int* in_sizes, int n_in,
                              void* d_out, int out_size)
{
    const float *depth=nullptr, *trans=nullptr, *img=nullptr, *K=nullptr;
    for (int i=0;i<n_in;i++){
        switch (in_sizes[i]) {
            case BATCH*WH:    depth = (const float*)d_in[i]; break;   // 9830400
            case BATCH*16:    trans = (const float*)d_in[i]; break;   // 512
            case BATCH*3*WH:  img   = (const float*)d_in[i]; break;   // 29491200
            case 9:           K     = (const float*)d_in[i]; break;
        }
    }
    // positional fallback (metadata order: depth_map, transforms, image, K)
    if (!depth && n_in > 0) depth = (const float*)d_in[0];
    if (!trans && n_in > 1) trans = (const float*)d_in[1];
    if (!img   && n_in > 2) img   = (const float*)d_in[2];
    if (!K     && n_in > 3) K     = (const float*)d_in[3];

    float* out = (float*)d_out;

    k_init<<<1,1>>>(K);
    dim3 grid(WH/4/256, BATCH);   // (300, 32)
    k_pass1<<<grid,256>>>(depth, trans, K);
    k_pass2<<<grid,256>>>(depth, trans, K, img, out);
}

// round 9
// speedup vs baseline: 1.3901x; 1.3901x over previous
#include <cuda_runtime.h>
#include <math.h>

#define BATCH 32
#define WG 640
#define HG 480
#define WH (WG*HG)          /* 307200 */
#define IMG_H 480
#define IMG_W 640

__device__ float g_max;
__device__ float g_neg_inf = -INFINITY;

// Fused per-batch matrices:
//   q = d * ([x,y,1] @ M) + c,  M = K^-1 @ T33 @ K (3x3),  c = T[3,0:3] @ K (3)
// uv = (q0, q1) / (q2 + 1e-4)
__device__ __forceinline__ void compute_mats(
    const float* __restrict__ K, const float* __restrict__ T,
    float* __restrict__ M, float* __restrict__ c)
{
    float a=K[0],b=K[1],cc=K[2],d=K[3],e=K[4],f=K[5],g=K[6],h=K[7],i=K[8];
    float det = a*(e*i - f*h) - b*(d*i - f*g) + cc*(d*h - e*g);
    float id = 1.0f/det;
    float Ki[9];
    Ki[0]=(e*i-f*h)*id; Ki[1]=(cc*h-b*i)*id; Ki[2]=(b*f-cc*e)*id;
    Ki[3]=(f*g-d*i)*id; Ki[4]=(a*i-cc*g)*id; Ki[5]=(cc*d-a*f)*id;
    Ki[6]=(d*h-e*g)*id; Ki[7]=(b*g-a*h)*id; Ki[8]=(a*e-b*d)*id;

    float G[9];   // T33 @ K
    #pragma unroll
    for (int r=0;r<3;r++)
        #pragma unroll
        for (int cl=0;cl<3;cl++)
            G[r*3+cl] = T[r*4+0]*K[cl] + T[r*4+1]*K[3+cl] + T[r*4+2]*K[6+cl];
    #pragma unroll
    for (int r=0;r<3;r++)
        #pragma unroll
        for (int cl=0;cl<3;cl++)
            M[r*3+cl] = Ki[r*3+0]*G[cl] + Ki[r*3+1]*G[3+cl] + Ki[r*3+2]*G[6+cl];
    #pragma unroll
    for (int cl=0;cl<3;cl++)
        c[cl] = T[12]*K[cl] + T[13]*K[3+cl] + T[14]*K[6+cl];
}

__device__ __forceinline__ void uv_fused(float d, float x, float y,
    const float* __restrict__ M, const float* __restrict__ c,
    float& u, float& v)
{
    float s0 = fmaf(x, M[0], fmaf(y, M[3], M[6]));
    float s1 = fmaf(x, M[1], fmaf(y, M[4], M[7]));
    float s2 = fmaf(x, M[2], fmaf(y, M[5], M[8]));
    float q0 = fmaf(d, s0, c[0]);
    float q1 = fmaf(d, s1, c[1]);
    float q2 = fmaf(d, s2, c[2]);
    float inv = 1.0f/(q2 + 1e-4f);
    u = q0*inv;
    v = q1*inv;
}

// Pass 1: global max of all uv components. 8 px/thread.
__global__ __launch_bounds__(256) void k_pass1(
    const float* __restrict__ depth, const float* __restrict__ trans,
    const float* __restrict__ Kp)
{
    __shared__ float sM[9], sc[3];
    int b = blockIdx.y;
    if (threadIdx.x == 0) {
        float Kl[9], Tl[16];
        #pragma unroll
        for (int i=0;i<9;i++)  Kl[i] = __ldg(Kp + i);
        #pragma unroll
        for (int i=0;i<16;i++) Tl[i] = __ldg(trans + b*16 + i);
        compute_mats(Kl, Tl, sM, sc);
    }
    __syncthreads();
    float M[9], c[3];
    #pragma unroll
    for (int i=0;i<9;i++) M[i]=sM[i];
    #pragma unroll
    for (int i=0;i<3;i++) c[i]=sc[i];

    int t = blockIdx.x*256 + threadIdx.x;
    int pix = t*8;
    int w = pix/HG;
    int h = pix - w*HG;
    float y = (float)w;

    const float4* dp = reinterpret_cast<const float4*>(depth + (size_t)b*WH + pix);
    float4 a4 = dp[0], b4 = dp[1];
    float dd[8] = {a4.x,a4.y,a4.z,a4.w, b4.x,b4.y,b4.z,b4.w};

    float m = -INFINITY;
    #pragma unroll
    for (int k=0;k<8;k++){
        float u,v;
        uv_fused(dd[k], (float)(h+k), y, M, c, u, v);
        m = fmaxf(m, fmaxf(u,v));
    }
    #pragma unroll
    for (int o=16;o>0;o>>=1) m = fmaxf(m, __shfl_xor_sync(0xffffffffu, m, o));

    __shared__ float sm[8];
    if ((threadIdx.x & 31)==0) sm[threadIdx.x>>5] = m;
    __syncthreads();
    if (threadIdx.x==0){
        float bm = sm[0];
        #pragma unroll
        for (int i=1;i<8;i++) bm = fmaxf(bm, sm[i]);
        if (bm >= 0.0f) atomicMax((int*)&g_max, __float_as_int(bm));
        else            atomicMin((unsigned int*)&g_max, __float_as_uint(bm));
    }
}

// Pass 2: normalize + bilinear grid_sample (zeros padding). 4 px/thread.
__global__ __launch_bounds__(256) void k_pass2(
    const float* __restrict__ depth, const float* __restrict__ trans,
    const float* __restrict__ Kp, const float* __restrict__ img,
    float* __restrict__ out)
{
    __shared__ float sM[9], sc[3];
    int b = blockIdx.y;
    if (threadIdx.x == 0) {
        float Kl[9], Tl[16];
        #pragma unroll
        for (int i=0;i<9;i++)  Kl[i] = __ldg(Kp + i);
        #pragma unroll
        for (int i=0;i<16;i++) Tl[i] = __ldg(trans + b*16 + i);
        compute_mats(Kl, Tl, sM, sc);
    }
    __syncthreads();
    float M[9], c[3];
    #pragma unroll
    for (int i=0;i<9;i++) M[i]=sM[i];
    #pragma unroll
    for (int i=0;i<3;i++) c[i]=sc[i];

    int t = blockIdx.x*256 + threadIdx.x;
    int pix = t*4;
    int w = pix/HG;
    int h = pix - w*HG;
    float y = (float)w;

    float Gm = g_max;
    // xs = (2*(u/Gm)-1 + 1)*(W/2) - 0.5 = u*(W/Gm) - 0.5  (same for ys with H)
    float fx = (float)IMG_W / Gm;
    float fy = (float)IMG_H / Gm;

    float4 d4 = *reinterpret_cast<const float4*>(depth + (size_t)b*WH + pix);
    float dd[4] = {d4.x, d4.y, d4.z, d4.w};

    const float* imgb = img + (size_t)b*3*WH;
    float res[3][4];

    #pragma unroll
    for (int k=0;k<4;k++){
        float u,v;
        uv_fused(dd[k], (float)(h+k), y, M, c, u, v);
        float xs = fmaf(u, fx, -0.5f);
        float ys = fmaf(v, fy, -0.5f);
        float x0f = floorf(xs), y0f = floorf(ys);
        float wx = xs - x0f,   wy = ys - y0f;
        float x1f = x0f + 1.0f, y1f = y0f + 1.0f;
        bool vx0 = (x0f >= 0.0f) && (x0f <= (float)(IMG_W-1));
        bool vx1 = (x1f >= 0.0f) && (x1f <= (float)(IMG_W-1));
        bool vy0 = (y0f >= 0.0f) && (y0f <= (float)(IMG_H-1));
        bool vy1 = (y1f >= 0.0f) && (y1f <= (float)(IMG_H-1));
        int x0i = (int)fminf(fmaxf(x0f,0.0f),(float)(IMG_W-1));
        int x1i = (int)fminf(fmaxf(x1f,0.0f),(float)(IMG_W-1));
        int y0i = (int)fminf(fmaxf(y0f,0.0f),(float)(IMG_H-1));
        int y1i = (int)fminf(fmaxf(y1f,0.0f),(float)(IMG_H-1));
        float w00 = (1.0f-wx)*(1.0f-wy);
        float w01 = wx*(1.0f-wy);
        float w10 = (1.0f-wx)*wy;
        float w11 = wx*wy;
        int i00 = y0i*IMG_W + x0i;
        int i01 = y0i*IMG_W + x1i;
        int i10 = y1i*IMG_W + x0i;
        int i11 = y1i*IMG_W + x1i;
        bool b00 = vx0 && vy0, b01 = vx1 && vy0, b10 = vx0 && vy1, b11 = vx1 && vy1;
        #pragma unroll
        for (int ch=0;ch<3;ch++){
            const float* ic = imgb + (size_t)ch*WH;
            float s = 0.0f;
            if (b00) s += __ldg(ic + i00) * w00;
            if (b01) s += __ldg(ic + i01) * w01;
            if (b10) s += __ldg(ic + i10) * w10;
            if (b11) s += __ldg(ic + i11) * w11;
            res[ch][k] = s;
        }
    }

    size_t ob = (size_t)b*3*WH + (size_t)w*HG + (size_t)h;
    #pragma unroll
    for (int ch=0;ch<3;ch++){
        float4 o = make_float4(res[ch][0], res[ch][1], res[ch][2], res[ch][3]);
        *reinterpret_cast<float4*>(out + ob + (size_t)ch*WH) = o;
    }
}

extern "C" void kernel_launch(void* const* d_in, const int* in_sizes, int n_in,
                              void* d_out, int out_size)
{
    const float *depth=nullptr, *trans=nullptr, *img=nullptr, *K=nullptr;
    for (int i=0;i<n_in;i++){
        switch (in_sizes[i]) {
            case BATCH*WH:    depth = (const float*)d_in[i]; break;   // 9830400
            case BATCH*16:    trans = (const float*)d_in[i]; break;   // 512
            case BATCH*3*WH:  img   = (const float*)d_in[i]; break;   // 29491200
            case 9:           K     = (const float*)d_in[i]; break;
        }
    }
    if (!depth && n_in > 0) depth = (const float*)d_in[0];
    if (!trans && n_in > 1) trans = (const float*)d_in[1];
    if (!img   && n_in > 2) img   = (const float*)d_in[2];
    if (!K     && n_in > 3) K     = (const float*)d_in[3];

    float* out = (float*)d_out;

    // Reset g_max to -inf with a tiny d2d memcpy node (replaces the k_init kernel).
    void *pmax = nullptr, *pninf = nullptr;
    cudaGetSymbolAddress(&pmax,  g_max);
    cudaGetSymbolAddress(&pninf, g_neg_inf);
    cudaMemcpyAsync(pmax, pninf, sizeof(float), cudaMemcpyDeviceToDevice);

    dim3 g1(WH/8/256, BATCH);   // (150, 32)
    dim3 g2(WH/4/256, BATCH);   // (300, 32)
    k_pass1<<<g1,256>>>(depth, trans, K);
    k_pass2<<<g2,256>>>(depth, trans, K, img, out);
}

// round 15
// speedup vs baseline: 1.6791x; 1.2079x over previous
#include <cuda_runtime.h>
#include <math.h>

#define BATCH 32
#define WG 640
#define HG 480
#define WH (WG*HG)          /* 307200 */
#define IMG_H 480
#define IMG_W 640

__device__ float g_max;
__device__ float g_neg_inf = -INFINITY;

__device__ __forceinline__ float frcp_fast(float x){
    float r; asm("rcp.approx.f32 %0, %1;" : "=f"(r) : "f"(x)); return r;
}

// Fused per-batch matrices:
//   q = d * ([x,y,1] @ M) + c,  M = K^-1 @ T33 @ K (3x3),  c = T[3,0:3] @ K (3)
// uv = (q0, q1) / (q2 + 1e-4)
__device__ __forceinline__ void compute_mats(
    const float* __restrict__ K, const float* __restrict__ T,
    float* __restrict__ M, float* __restrict__ c)
{
    float a=K[0],b=K[1],cc=K[2],d=K[3],e=K[4],f=K[5],g=K[6],h=K[7],i=K[8];
    float det = a*(e*i - f*h) - b*(d*i - f*g) + cc*(d*h - e*g);
    float id = 1.0f/det;
    float Ki[9];
    Ki[0]=(e*i-f*h)*id; Ki[1]=(cc*h-b*i)*id; Ki[2]=(b*f-cc*e)*id;
    Ki[3]=(f*g-d*i)*id; Ki[4]=(a*i-cc*g)*id; Ki[5]=(cc*d-a*f)*id;
    Ki[6]=(d*h-e*g)*id; Ki[7]=(b*g-a*h)*id; Ki[8]=(a*e-b*d)*id;

    float G[9];   // T33 @ K
    #pragma unroll
    for (int r=0;r<3;r++)
        #pragma unroll
        for (int cl=0;cl<3;cl++)
            G[r*3+cl] = T[r*4+0]*K[cl] + T[r*4+1]*K[3+cl] + T[r*4+2]*K[6+cl];
    #pragma unroll
    for (int r=0;r<3;r++)
        #pragma unroll
        for (int cl=0;cl<3;cl++)
            M[r*3+cl] = Ki[r*3+0]*G[cl] + Ki[r*3+1]*G[3+cl] + Ki[r*3+2]*G[6+cl];
    #pragma unroll
    for (int cl=0;cl<3;cl++)
        c[cl] = T[12]*K[cl] + T[13]*K[3+cl] + T[14]*K[6+cl];
}

__device__ __forceinline__ void uv_fused(float d, float x, float y,
    const float* __restrict__ M, const float* __restrict__ c,
    float& u, float& v)
{
    float s0 = fmaf(x, M[0], fmaf(y, M[3], M[6]));
    float s1 = fmaf(x, M[1], fmaf(y, M[4], M[7]));
    float s2 = fmaf(x, M[2], fmaf(y, M[5], M[8]));
    float q0 = fmaf(d, s0, c[0]);
    float q1 = fmaf(d, s1, c[1]);
    float q2 = fmaf(d, s2, c[2]);
    float inv = frcp_fast(q2 + 1e-4f);
    u = q0*inv;
    v = q1*inv;
}

// Pass 1: global max of all uv components. 8 px/thread.
__global__ __launch_bounds__(256) void k_pass1(
    const float* __restrict__ depth, const float* __restrict__ trans,
    const float* __restrict__ Kp)
{
    __shared__ float sM[9], sc[3];
    int b = blockIdx.y;
    if (threadIdx.x == 0) {
        float Kl[9], Tl[16];
        #pragma unroll
        for (int i=0;i<9;i++)  Kl[i] = __ldg(Kp + i);
        #pragma unroll
        for (int i=0;i<16;i++) Tl[i] = __ldg(trans + b*16 + i);
        compute_mats(Kl, Tl, sM, sc);
    }
    __syncthreads();
    float M[9], c[3];
    #pragma unroll
    for (int i=0;i<9;i++) M[i]=sM[i];
    #pragma unroll
    for (int i=0;i<3;i++) c[i]=sc[i];

    int t = blockIdx.x*256 + threadIdx.x;
    int pix = t*8;
    int w = pix/HG;
    int h = pix - w*HG;
    float y = (float)w;

    const float4* dp = reinterpret_cast<const float4*>(depth + (size_t)b*WH + pix);
    float4 a4 = dp[0], b4 = dp[1];
    float dd[8] = {a4.x,a4.y,a4.z,a4.w, b4.x,b4.y,b4.z,b4.w};

    float m = -INFINITY;
    #pragma unroll
    for (int k=0;k<8;k++){
        float u,v;
        uv_fused(dd[k], (float)(h+k), y, M, c, u, v);
        m = fmaxf(m, fmaxf(u,v));
    }
    #pragma unroll
    for (int o=16;o>0;o>>=1) m = fmaxf(m, __shfl_xor_sync(0xffffffffu, m, o));

    __shared__ float sm[8];
    if ((threadIdx.x & 31)==0) sm[threadIdx.x>>5] = m;
    __syncthreads();
    if (threadIdx.x==0){
        float bm = sm[0];
        #pragma unroll
        for (int i=1;i<8;i++) bm = fmaxf(bm, sm[i]);
        if (bm >= 0.0f) atomicMax((int*)&g_max, __float_as_int(bm));
        else            atomicMin((unsigned int*)&g_max, __float_as_uint(bm));
    }
}

// Pass 2: normalize + bilinear grid_sample (zeros padding). 4 px/thread.
// Integer-floor path: floor via __float2int_rd, validity via unsigned compares,
// no clamps (loads are predicated, raw index relationships i00/+1/+W/+W+1 exact).
__global__ __launch_bounds__(256) void k_pass2(
    const float* __restrict__ depth, const float* __restrict__ trans,
    const float* __restrict__ Kp, const float* __restrict__ img,
    float* __restrict__ out)
{
    __shared__ float sM[9], sc[3];
    int b = blockIdx.y;
    if (threadIdx.x == 0) {
        float Kl[9], Tl[16];
        #pragma unroll
        for (int i=0;i<9;i++)  Kl[i] = __ldg(Kp + i);
        #pragma unroll
        for (int i=0;i<16;i++) Tl[i] = __ldg(trans + b*16 + i);
        compute_mats(Kl, Tl, sM, sc);
    }
    __syncthreads();
    float M[9], c[3];
    #pragma unroll
    for (int i=0;i<9;i++) M[i]=sM[i];
    #pragma unroll
    for (int i=0;i<3;i++) c[i]=sc[i];

    int t = blockIdx.x*256 + threadIdx.x;
    int pix = t*4;
    int w = pix/HG;
    int h = pix - w*HG;
    float y = (float)w;

    float Gm = g_max;
    // xs = u*(W/Gm) - 0.5 ; ys = v*(H/Gm) - 0.5
    float ig = frcp_fast(Gm);
    float fx = (float)IMG_W * ig;
    float fy = (float)IMG_H * ig;

    float4 d4 = *reinterpret_cast<const float4*>(depth + (size_t)b*WH + pix);
    float dd[4] = {d4.x, d4.y, d4.z, d4.w};

    const float* imgb = img + (size_t)b*3*WH;
    float res[3][4];

    #pragma unroll
    for (int k=0;k<4;k++){
        float u,v;
        uv_fused(dd[k], (float)(h+k), y, M, c, u, v);
        float xs = fmaf(u, fx, -0.5f);
        float ys = fmaf(v, fy, -0.5f);
        int x0 = __float2int_rd(xs);      // floor
        int y0 = __float2int_rd(ys);
        float wx = xs - __int2float_rn(x0);
        float wy = ys - __int2float_rn(y0);
        float omx = 1.0f - wx, omy = 1.0f - wy;

        bool vx0 = ((unsigned)x0       < (unsigned)IMG_W);
        bool vx1 = ((unsigned)(x0 + 1) < (unsigned)IMG_W);
        bool vy0 = ((unsigned)y0       < (unsigned)IMG_H);
        bool vy1 = ((unsigned)(y0 + 1) < (unsigned)IMG_H);
        bool b00 = vx0 && vy0, b01 = vx1 && vy0;
        bool b10 = vx0 && vy1, b11 = vx1 && vy1;

        float w00 = omx*omy, w01 = wx*omy, w10 = omx*wy, w11 = wx*wy;

        int i00 = y0*IMG_W + x0;          // raw; deref only when valid
        #pragma unroll
        for (int ch=0;ch<3;ch++){
            const float* p = imgb + (size_t)ch*WH + i00;
            float s = 0.0f;
            if (b00) s = fmaf(__ldg(p),           w00, s);
            if (b01) s = fmaf(__ldg(p + 1),       w01, s);
            if (b10) s = fmaf(__ldg(p + IMG_W),   w10, s);
            if (b11) s = fmaf(__ldg(p + IMG_W+1), w11, s);
            res[ch][k] = s;
        }
    }

    size_t ob = (size_t)b*3*WH + (size_t)w*HG + (size_t)h;
    #pragma unroll
    for (int ch=0;ch<3;ch++){
        float4 o = make_float4(res[ch][0], res[ch][1], res[ch][2], res[ch][3]);
        *reinterpret_cast<float4*>(out + ob + (size_t)ch*WH) = o;
    }
}

extern "C" void kernel_launch(void* const* d_in, const int* in_sizes, int n_in,
                              void* d_out, int out_size)
{
    const float *depth=nullptr, *trans=nullptr, *img=nullptr, *K=nullptr;
    for (int i=0;i<n_in;i++){
        switch (in_sizes[i]) {
            case BATCH*WH:    depth = (const float*)d_in[i]; break;   // 9830400
            case BATCH*16:    trans = (const float*)d_in[i]; break;   // 512
            case BATCH*3*WH:  img   = (const float*)d_in[i]; break;   // 29491200
            case 9:           K     = (const float*)d_in[i]; break;
        }
    }
    if (!depth && n_in > 0) depth = (const float*)d_in[0];
    if (!trans && n_in > 1) trans = (const float*)d_in[1];
    if (!img   && n_in > 2) img   = (const float*)d_in[2];
    if (!K     && n_in > 3) K     = (const float*)d_in[3];

    float* out = (float*)d_out;

    // Reset g_max to -inf with a tiny d2d memcpy node.
    void *pmax = nullptr, *pninf = nullptr;
    cudaGetSymbolAddress(&pmax,  g_max);
    cudaGetSymbolAddress(&pninf, g_neg_inf);
    cudaMemcpyAsync(pmax, pninf, sizeof(float), cudaMemcpyDeviceToDevice);

    dim3 g1(WH/8/256, BATCH);   // (150, 32)
    dim3 g2(WH/4/256, BATCH);   // (300, 32)
    k_pass1<<<g1,256>>>(depth, trans, K);
    k_pass2<<<g2,256>>>(depth, trans, K, img, out);
}